// round 7
// baseline (speedup 1.0000x reference)
#include <cuda_runtime.h>
#include <cstdint>

#define N_NODES 50000
#define N_EDGES 800000
#define FDIM    64
#define NRELS   8

// ---- scratch (allocation-free rule: __device__ globals) ----
// 16B-aligned: accessed as float4 in k_gemm stores and k_edges loads.
__device__ __align__(16) float g_hw[(size_t)NRELS * N_NODES * FDIM];  // 102.4 MB
__device__ int g_deg[N_NODES];

// ---------------------------------------------------------------------------
// K0: zero the output accumulator (d_out is poisoned each replay) and g_deg.
// ---------------------------------------------------------------------------
__global__ void k_zero(float4* __restrict__ out) {
    int i = blockIdx.x * blockDim.x + threadIdx.x;
    if (i < N_NODES * (FDIM / 4)) out[i] = make_float4(0.f, 0.f, 0.f, 0.f);
    if (i < N_NODES) g_deg[i] = 0;
}

// ---------------------------------------------------------------------------
// K1: in-degree of each destination node.
// ---------------------------------------------------------------------------
__global__ void k_deg(const int* __restrict__ dst) {
    int e = blockIdx.x * blockDim.x + threadIdx.x;
    if (e < N_EDGES) atomicAdd(&g_deg[dst[e]], 1);
}

// ---------------------------------------------------------------------------
// K2: hw[r] = features @ W_r.  Block = 128 nodes x 64 cols for one relation.
// 256 threads, each computes a 4x8 micro-tile (32 accumulators).
// A staged in shared with +1 padding (row stride 65 floats): column reads
// As[row][k] across the 4 row-groups land on banks k, k+4, k+8, k+12 —
// conflict-free. NOTE: stride 65 rows are NOT 16B-aligned, so staging must
// use scalar stores (the float4 shared store here caused the earlier
// misaligned-address fault).
// ---------------------------------------------------------------------------
#define TILE_M 128
#define GEMM_THREADS 256
#define SMEM_BYTES ((TILE_M * 65 + FDIM * FDIM) * 4)   // 33280 + 16384 = 49664

__global__ __launch_bounds__(GEMM_THREADS)
void k_gemm(const float* __restrict__ feat, const float* __restrict__ W) {
    extern __shared__ float sm[];
    float (*As)[65] = (float (*)[65])sm;                     // [128][65]
    float (*Ws)[FDIM] = (float (*)[FDIM])(sm + TILE_M * 65); // [64][64], 16B-aligned base

    const int r    = blockIdx.y;
    const int row0 = blockIdx.x * TILE_M;
    const int tid  = threadIdx.x;

    // stage W_r (4096 floats = 1024 float4; Ws base offset 33280 % 16 == 0)
    const float4* Wg = (const float4*)(W + (size_t)r * FDIM * FDIM);
    #pragma unroll
    for (int i = tid; i < FDIM * FDIM / 4; i += GEMM_THREADS)
        ((float4*)Ws)[i] = Wg[i];

    // stage A tile (128 rows x 64 cols): float4 global load, SCALAR shared
    // stores (padded stride => rows not 16B-aligned). Zero-pad past N.
    #pragma unroll
    for (int i = tid; i < TILE_M * (FDIM / 4); i += GEMM_THREADS) {
        int rr = i >> 4, cc = i & 15;
        int n = row0 + rr;
        float4 v = (n < N_NODES) ? ((const float4*)feat)[(size_t)n * 16 + cc]
                                 : make_float4(0.f, 0.f, 0.f, 0.f);
        float* p = &As[rr][cc * 4];
        p[0] = v.x; p[1] = v.y; p[2] = v.z; p[3] = v.w;
    }
    __syncthreads();

    const int tcol = tid & 7;   // 8 col-groups of 8 columns
    const int trow = tid >> 3;  // 32 row-groups of 4 rows

    float acc[4][8];
    #pragma unroll
    for (int i = 0; i < 4; i++)
        #pragma unroll
        for (int j = 0; j < 8; j++) acc[i][j] = 0.f;

    #pragma unroll 8
    for (int k = 0; k < FDIM; k++) {
        float a[4];
        #pragma unroll
        for (int i = 0; i < 4; i++) a[i] = As[trow * 4 + i][k];
        float4 b0 = *(const float4*)&Ws[k][tcol * 8];      // Ws rows 256B: aligned
        float4 b1 = *(const float4*)&Ws[k][tcol * 8 + 4];
        float b[8] = {b0.x, b0.y, b0.z, b0.w, b1.x, b1.y, b1.z, b1.w};
        #pragma unroll
        for (int i = 0; i < 4; i++)
            #pragma unroll
            for (int j = 0; j < 8; j++)
                acc[i][j] = fmaf(a[i], b[j], acc[i][j]);
    }

    float* hw = g_hw + (size_t)r * N_NODES * FDIM;
    #pragma unroll
    for (int i = 0; i < 4; i++) {
        int n = row0 + trow * 4 + i;
        if (n < N_NODES) {
            float4 v0 = {acc[i][0], acc[i][1], acc[i][2], acc[i][3]};
            float4 v1 = {acc[i][4], acc[i][5], acc[i][6], acc[i][7]};
            float* p = hw + (size_t)n * FDIM + tcol * 8;   // 32B-aligned (g_hw align 16)
            ((float4*)p)[0] = v0;
            ((float4*)p)[1] = v1;
        }
    }
}

// ---------------------------------------------------------------------------
// K3: edge scatter. 16 lanes per edge, each handles one float4 (64 floats).
// Unscaled sum into out[dst]; the /deg scaling is folded into the epilogue.
// red.global.add.v4.f32 (no return, 16B/op). hw (102 MB) + out (12.8 MB)
// are L2-resident -> LTS-bound phase.
// ---------------------------------------------------------------------------
__global__ void k_edges(const int* __restrict__ src, const int* __restrict__ dst,
                        const int* __restrict__ et, float* __restrict__ out) {
    int t = blockIdx.x * blockDim.x + threadIdx.x;
    int e = t >> 4;
    int l = t & 15;
    if (e >= N_EDGES) return;
    int s = __ldg(&src[e]);
    int d = __ldg(&dst[e]);
    int r = __ldg(&et[e]);
    const float4* row = (const float4*)(g_hw + ((size_t)r * N_NODES + s) * FDIM);
    float4 v = row[l];
    float* o = out + (size_t)d * FDIM + l * 4;
    asm volatile("red.global.add.v4.f32 [%0], {%1,%2,%3,%4};"
                 :: "l"(o), "f"(v.x), "f"(v.y), "f"(v.z), "f"(v.w) : "memory");
}

// ---------------------------------------------------------------------------
// K4: epilogue.  out = deg>0 ? relu(0.2*f + (0.8/deg)*sum) : f
// ---------------------------------------------------------------------------
__global__ void k_final(const float* __restrict__ feat, float* __restrict__ out) {
    int i = blockIdx.x * blockDim.x + threadIdx.x;   // over N*16 float4s
    if (i >= N_NODES * (FDIM / 4)) return;
    int v = i >> 4;
    float4 f = ((const float4*)feat)[i];
    int dg = g_deg[v];
    float4 res;
    if (dg > 0) {
        float4 m = ((float4*)out)[i];
        float inv = 0.8f / (float)dg;
        res.x = fmaxf(fmaf(m.x, inv, 0.2f * f.x), 0.f);
        res.y = fmaxf(fmaf(m.y, inv, 0.2f * f.y), 0.f);
        res.z = fmaxf(fmaf(m.z, inv, 0.2f * f.z), 0.f);
        res.w = fmaxf(fmaf(m.w, inv, 0.2f * f.w), 0.f);
    } else {
        res = f;
    }
    ((float4*)out)[i] = res;
}

// ---------------------------------------------------------------------------
extern "C" void kernel_launch(void* const* d_in, const int* in_sizes, int n_in,
                              void* d_out, int out_size) {
    const float* feat = (const float*)d_in[0];   // [50000, 64] f32
    const float* W    = (const float*)d_in[1];   // [8, 64, 64] f32
    const int*   src  = (const int*)d_in[2];     // [800000] i32
    const int*   dst  = (const int*)d_in[3];     // [800000] i32
    const int*   et   = (const int*)d_in[4];     // [800000] i32
    float* out = (float*)d_out;                  // [50000, 64] f32

    static bool attr_set = false;
    if (!attr_set) {
        cudaFuncSetAttribute(k_gemm, cudaFuncAttributeMaxDynamicSharedMemorySize,
                             SMEM_BYTES);
        attr_set = true;
    }

    const int ZN = N_NODES * (FDIM / 4);         // 800000
    k_zero<<<(ZN + 255) / 256, 256>>>((float4*)out);
    k_deg<<<(N_EDGES + 255) / 256, 256>>>(dst);

    dim3 ggrid((N_NODES + TILE_M - 1) / TILE_M, NRELS);   // (391, 8)
    k_gemm<<<ggrid, GEMM_THREADS, SMEM_BYTES>>>(feat, W);

    k_edges<<<(N_EDGES * 16 + 255) / 256, 256>>>(src, dst, et, out);
    k_final<<<(ZN + 255) / 256, 256>>>(feat, out);
}

// round 8
// speedup vs baseline: 1.5076x; 1.5076x over previous
#include <cuda_runtime.h>
#include <cstdint>

#define N_NODES 50000
#define N_EDGES 800000
#define FDIM    64
#define NRELS   8

// ---- scratch (allocation-free rule: __device__ globals) ----
__device__ __align__(16) float g_hw[(size_t)NRELS * N_NODES * FDIM];  // 102.4 MB
__device__ __align__(16) int2  g_epack[N_EDGES];                      // {r*N+src, dst}
__device__ int g_deg[N_NODES];

// ---------------------------------------------------------------------------
// K0: zero the output accumulator (d_out is poisoned each replay) and g_deg.
// ---------------------------------------------------------------------------
__global__ void k_zero(float4* __restrict__ out) {
    int i = blockIdx.x * blockDim.x + threadIdx.x;
    if (i < N_NODES * (FDIM / 4)) out[i] = make_float4(0.f, 0.f, 0.f, 0.f);
    if (i < N_NODES) g_deg[i] = 0;
}

// ---------------------------------------------------------------------------
// K1: fused degree histogram + edge-index packing.
// g_epack[e] = { etype*N + src  (direct row index into g_hw), dst }.
// ---------------------------------------------------------------------------
__global__ void k_pack_deg(const int* __restrict__ src, const int* __restrict__ dst,
                           const int* __restrict__ et) {
    int e = blockIdx.x * blockDim.x + threadIdx.x;
    if (e >= N_EDGES) return;
    int d = dst[e];
    g_epack[e] = make_int2(et[e] * N_NODES + src[e], d);
    atomicAdd(&g_deg[d], 1);
}

// ---------------------------------------------------------------------------
// K2: hw[r] = features @ W_r via tf32 mma.sync (m16n8k8).
// Block = 128 rows x 64 cols for one relation; 4 warps, each warp owns a
// 32-row strip (2 m16 tiles x 8 n8 tiles, K=64 in 8 k-steps).
// A fragments: scalar LDG from global (each element read once/relation),
// rounded to tf32 with cvt.rna. W staged in smem pre-rounded to tf32 with
// row stride 72 floats: B-frag bank = (8*kc + gid) + 8*nt (mod 32), all 32
// lanes distinct -> conflict-free LDS.
// ---------------------------------------------------------------------------
#define GEMM_THREADS 128
#define W_STRIDE 72

__device__ __forceinline__ uint32_t f2tf32(float x) {
    uint32_t u;
    asm("cvt.rna.tf32.f32 %0, %1;" : "=r"(u) : "f"(x));
    return u;
}

__global__ __launch_bounds__(GEMM_THREADS)
void k_gemm_tc(const float* __restrict__ feat, const float* __restrict__ W) {
    __shared__ uint32_t Ws[FDIM * W_STRIDE];   // 18432 B

    const int r    = blockIdx.y;
    const int row0 = blockIdx.x * 128;
    const int tid  = threadIdx.x;
    const int warp = tid >> 5;
    const int lane = tid & 31;
    const int gid  = lane >> 2;   // 0..7
    const int kc   = lane & 3;    // 0..3

    // stage W_r pre-rounded to tf32
    const float* Wg = W + (size_t)r * FDIM * FDIM;
    #pragma unroll
    for (int i = tid; i < FDIM * FDIM; i += GEMM_THREADS)
        Ws[(i >> 6) * W_STRIDE + (i & 63)] = f2tf32(Wg[i]);
    __syncthreads();

    // accumulators: 2 m-tiles x 8 n-tiles x 4 regs
    float c[2][8][4];
    #pragma unroll
    for (int mt = 0; mt < 2; mt++)
        #pragma unroll
        for (int nt = 0; nt < 8; nt++)
            #pragma unroll
            for (int i = 0; i < 4; i++) c[mt][nt][i] = 0.f;

    const int wrow = row0 + warp * 32;
    // clamped fragment rows (clamp keeps loads in-bounds; stores are predicated)
    int fr0[2], fr1[2];
    #pragma unroll
    for (int mt = 0; mt < 2; mt++) {
        int r0 = wrow + mt * 16 + gid;
        int r1 = r0 + 8;
        fr0[mt] = r0 < N_NODES ? r0 : N_NODES - 1;
        fr1[mt] = r1 < N_NODES ? r1 : N_NODES - 1;
    }

    #pragma unroll
    for (int ks = 0; ks < 8; ks++) {
        const int k0 = ks * 8;
        uint32_t a[2][4];
        #pragma unroll
        for (int mt = 0; mt < 2; mt++) {
            a[mt][0] = f2tf32(__ldg(&feat[(size_t)fr0[mt] * FDIM + k0 + kc]));
            a[mt][1] = f2tf32(__ldg(&feat[(size_t)fr1[mt] * FDIM + k0 + kc]));
            a[mt][2] = f2tf32(__ldg(&feat[(size_t)fr0[mt] * FDIM + k0 + kc + 4]));
            a[mt][3] = f2tf32(__ldg(&feat[(size_t)fr1[mt] * FDIM + k0 + kc + 4]));
        }
        #pragma unroll
        for (int nt = 0; nt < 8; nt++) {
            uint32_t b0 = Ws[(k0 + kc) * W_STRIDE + nt * 8 + gid];
            uint32_t b1 = Ws[(k0 + kc + 4) * W_STRIDE + nt * 8 + gid];
            #pragma unroll
            for (int mt = 0; mt < 2; mt++) {
                asm volatile(
                    "mma.sync.aligned.m16n8k8.row.col.f32.tf32.tf32.f32 "
                    "{%0,%1,%2,%3}, {%4,%5,%6,%7}, {%8,%9}, {%0,%1,%2,%3};"
                    : "+f"(c[mt][nt][0]), "+f"(c[mt][nt][1]),
                      "+f"(c[mt][nt][2]), "+f"(c[mt][nt][3])
                    : "r"(a[mt][0]), "r"(a[mt][1]), "r"(a[mt][2]), "r"(a[mt][3]),
                      "r"(b0), "r"(b1));
            }
        }
    }

    // epilogue: c0,c1 -> row gid, cols 2kc..; c2,c3 -> row gid+8
    float* hw = g_hw + (size_t)r * N_NODES * FDIM;
    #pragma unroll
    for (int mt = 0; mt < 2; mt++) {
        int r0 = wrow + mt * 16 + gid;
        int r1 = r0 + 8;
        #pragma unroll
        for (int nt = 0; nt < 8; nt++) {
            int col = nt * 8 + 2 * kc;
            if (r0 < N_NODES)
                *(float2*)&hw[(size_t)r0 * FDIM + col] =
                    make_float2(c[mt][nt][0], c[mt][nt][1]);
            if (r1 < N_NODES)
                *(float2*)&hw[(size_t)r1 * FDIM + col] =
                    make_float2(c[mt][nt][2], c[mt][nt][3]);
        }
    }
}

// ---------------------------------------------------------------------------
// K3: edge scatter. 16 lanes per edge, one float4 each. Packed index load
// (1 LDG.64) + payload LDG.128 + red.global.add.v4.f32. Unscaled sum; the
// /deg scaling is folded into the epilogue.
// ---------------------------------------------------------------------------
__global__ void k_edges(float* __restrict__ out) {
    int t = blockIdx.x * blockDim.x + threadIdx.x;
    int e = t >> 4;
    int l = t & 15;
    if (e >= N_EDGES) return;
    int2 idx = __ldg(&g_epack[e]);
    const float4* row = (const float4*)(g_hw + (size_t)idx.x * FDIM);
    float4 v = __ldg(&row[l]);
    float* o = out + (size_t)idx.y * FDIM + l * 4;
    asm volatile("red.global.add.v4.f32 [%0], {%1,%2,%3,%4};"
                 :: "l"(o), "f"(v.x), "f"(v.y), "f"(v.z), "f"(v.w) : "memory");
}

// ---------------------------------------------------------------------------
// K4: epilogue.  out = deg>0 ? relu(0.2*f + (0.8/deg)*sum) : f
// ---------------------------------------------------------------------------
__global__ void k_final(const float* __restrict__ feat, float* __restrict__ out) {
    int i = blockIdx.x * blockDim.x + threadIdx.x;   // over N*16 float4s
    if (i >= N_NODES * (FDIM / 4)) return;
    int v = i >> 4;
    float4 f = ((const float4*)feat)[i];
    int dg = g_deg[v];
    float4 res;
    if (dg > 0) {
        float4 m = ((float4*)out)[i];
        float inv = 0.8f / (float)dg;
        res.x = fmaxf(fmaf(m.x, inv, 0.2f * f.x), 0.f);
        res.y = fmaxf(fmaf(m.y, inv, 0.2f * f.y), 0.f);
        res.z = fmaxf(fmaf(m.z, inv, 0.2f * f.z), 0.f);
        res.w = fmaxf(fmaf(m.w, inv, 0.2f * f.w), 0.f);
    } else {
        res = f;
    }
    ((float4*)out)[i] = res;
}

// ---------------------------------------------------------------------------
extern "C" void kernel_launch(void* const* d_in, const int* in_sizes, int n_in,
                              void* d_out, int out_size) {
    const float* feat = (const float*)d_in[0];   // [50000, 64] f32
    const float* W    = (const float*)d_in[1];   // [8, 64, 64] f32
    const int*   src  = (const int*)d_in[2];     // [800000] i32
    const int*   dst  = (const int*)d_in[3];     // [800000] i32
    const int*   et   = (const int*)d_in[4];     // [800000] i32
    float* out = (float*)d_out;                  // [50000, 64] f32

    const int ZN = N_NODES * (FDIM / 4);         // 800000
    k_zero<<<(ZN + 255) / 256, 256>>>((float4*)out);
    k_pack_deg<<<(N_EDGES + 255) / 256, 256>>>(src, dst, et);

    dim3 ggrid((N_NODES + 127) / 128, NRELS);    // (391, 8)
    k_gemm_tc<<<ggrid, GEMM_THREADS>>>(feat, W);

    k_edges<<<(N_EDGES * 16 + 255) / 256, 256>>>(out);
    k_final<<<(ZN + 255) / 256, 256>>>(feat, out);
}

// round 9
// speedup vs baseline: 1.6049x; 1.0645x over previous
#include <cuda_runtime.h>
#include <cstdint>

#define N_NODES 50000
#define N_EDGES 800000
#define FDIM    64
#define NRELS   8
#define KDIM    (NRELS * FDIM)   // 512

// ---- scratch (allocation-free rule: __device__ globals) ----
// S[n, r, d] node-major accumulator = [50000, 512] fp32 (102.4 MB).
__device__ __align__(16) float g_S[(size_t)N_NODES * KDIM];
__device__ __align__(16) int2  g_epack[N_EDGES];   // {src, dst*8+etype}
__device__ int g_deg[N_NODES];

// ---------------------------------------------------------------------------
// K0: zero the scatter accumulator S and the degree array.
// (d_out no longer needs zeroing: the fused GEMM epilogue writes every elem.)
// ---------------------------------------------------------------------------
__global__ void k_zero() {
    size_t i = (size_t)blockIdx.x * blockDim.x + threadIdx.x;
    if (i < (size_t)N_NODES * (KDIM / 4))
        ((float4*)g_S)[i] = make_float4(0.f, 0.f, 0.f, 0.f);
    if (i < N_NODES) g_deg[i] = 0;
}

// ---------------------------------------------------------------------------
// K1: fused degree histogram + edge-index packing.
// g_epack[e] = { src (feat row), dst*8+etype (S row) }.
// ---------------------------------------------------------------------------
__global__ void k_pack_deg(const int* __restrict__ src, const int* __restrict__ dst,
                           const int* __restrict__ et) {
    int e = blockIdx.x * blockDim.x + threadIdx.x;
    if (e >= N_EDGES) return;
    int d = dst[e];
    g_epack[e] = make_int2(src[e], d * NRELS + et[e]);
    atomicAdd(&g_deg[d], 1);
}

// ---------------------------------------------------------------------------
// K2: edge scatter of RAW features. 16 lanes per edge, one float4 each.
// Gather source = feat (12.8 MB, fully L2-resident). RED target = g_S
// (102.4 MB, dirty-L2). No DRAM stream -> LTS-bound phase.
// ---------------------------------------------------------------------------
__global__ void k_scatter(const float4* __restrict__ feat4) {
    int t = blockIdx.x * blockDim.x + threadIdx.x;
    int e = t >> 4;
    int l = t & 15;
    if (e >= N_EDGES) return;
    int2 idx = __ldg(&g_epack[e]);
    float4 v = __ldg(&feat4[(size_t)idx.x * (FDIM / 4) + l]);
    float* o = g_S + (size_t)idx.y * FDIM + l * 4;
    asm volatile("red.global.add.v4.f32 [%0], {%1,%2,%3,%4};"
                 :: "l"(o), "f"(v.x), "f"(v.y), "f"(v.z), "f"(v.w) : "memory");
}

// ---------------------------------------------------------------------------
// K3: fused GEMM + epilogue.
//   M = S[50000, 512] @ Wcat[512, 64]   (Wcat = weight_r viewed as [R*D, F])
//   out = deg>0 ? relu(0.2*feat + (0.8/deg)*M) : feat
// tf32 mma.sync m16n8k8. Block = 128 rows x 64 cols, 4 warps, each warp a
// 32-row strip (2 m16 x 8 n8 tiles). K=512 done as 8 slices of 64; each
// slice's W staged in smem (stride 72 -> conflict-free B-frag LDS), A frags
// scalar-LDG'd from dirty-L2 g_S with cvt.rna tf32 rounding.
// ---------------------------------------------------------------------------
#define GEMM_THREADS 128
#define W_STRIDE 72

__device__ __forceinline__ uint32_t f2tf32(float x) {
    uint32_t u;
    asm("cvt.rna.tf32.f32 %0, %1;" : "=r"(u) : "f"(x));
    return u;
}

__global__ __launch_bounds__(GEMM_THREADS)
void k_gemm_final(const float* __restrict__ feat, const float* __restrict__ W,
                  float* __restrict__ out) {
    __shared__ uint32_t Ws[FDIM * W_STRIDE];   // 18432 B

    const int row0 = blockIdx.x * 128;
    const int tid  = threadIdx.x;
    const int warp = tid >> 5;
    const int lane = tid & 31;
    const int gid  = lane >> 2;   // 0..7
    const int kc   = lane & 3;    // 0..3

    // accumulators: 2 m-tiles x 8 n-tiles x 4 regs
    float c[2][8][4];
    #pragma unroll
    for (int mt = 0; mt < 2; mt++)
        #pragma unroll
        for (int nt = 0; nt < 8; nt++)
            #pragma unroll
            for (int i = 0; i < 4; i++) c[mt][nt][i] = 0.f;

    const int wrow = row0 + warp * 32;
    // clamped fragment rows (loads stay in-bounds; stores predicated)
    int fr0[2], fr1[2];
    #pragma unroll
    for (int mt = 0; mt < 2; mt++) {
        int r0 = wrow + mt * 16 + gid;
        int r1 = r0 + 8;
        fr0[mt] = r0 < N_NODES ? r0 : N_NODES - 1;
        fr1[mt] = r1 < N_NODES ? r1 : N_NODES - 1;
    }

    // K = 512 in 8 slices of 64 (slice rs == relation rs of Wcat)
    for (int rs = 0; rs < NRELS; rs++) {
        __syncthreads();
        const float* Wg = W + (size_t)rs * FDIM * FDIM;
        #pragma unroll
        for (int i = tid; i < FDIM * FDIM; i += GEMM_THREADS)
            Ws[(i >> 6) * W_STRIDE + (i & 63)] = f2tf32(Wg[i]);
        __syncthreads();

        const size_t kbase = (size_t)rs * FDIM;
        #pragma unroll
        for (int ks = 0; ks < 8; ks++) {
            const int k0 = ks * 8;
            uint32_t a[2][4];
            #pragma unroll
            for (int mt = 0; mt < 2; mt++) {
                const float* p0 = g_S + (size_t)fr0[mt] * KDIM + kbase + k0 + kc;
                const float* p1 = g_S + (size_t)fr1[mt] * KDIM + kbase + k0 + kc;
                a[mt][0] = f2tf32(__ldg(p0));
                a[mt][1] = f2tf32(__ldg(p1));
                a[mt][2] = f2tf32(__ldg(p0 + 4));
                a[mt][3] = f2tf32(__ldg(p1 + 4));
            }
            #pragma unroll
            for (int nt = 0; nt < 8; nt++) {
                uint32_t b0 = Ws[(k0 + kc) * W_STRIDE + nt * 8 + gid];
                uint32_t b1 = Ws[(k0 + kc + 4) * W_STRIDE + nt * 8 + gid];
                #pragma unroll
                for (int mt = 0; mt < 2; mt++) {
                    asm volatile(
                        "mma.sync.aligned.m16n8k8.row.col.f32.tf32.tf32.f32 "
                        "{%0,%1,%2,%3}, {%4,%5,%6,%7}, {%8,%9}, {%0,%1,%2,%3};"
                        : "+f"(c[mt][nt][0]), "+f"(c[mt][nt][1]),
                          "+f"(c[mt][nt][2]), "+f"(c[mt][nt][3])
                        : "r"(a[mt][0]), "r"(a[mt][1]), "r"(a[mt][2]), "r"(a[mt][3]),
                          "r"(b0), "r"(b1));
                }
            }
        }
    }

    // fused epilogue: out = deg>0 ? relu(0.2*feat + (0.8/deg)*M) : feat
    #pragma unroll
    for (int mt = 0; mt < 2; mt++) {
        int r0 = wrow + mt * 16 + gid;
        int r1 = r0 + 8;
        bool v0 = r0 < N_NODES, v1 = r1 < N_NODES;
        int dg0 = v0 ? g_deg[r0] : 0;
        int dg1 = v1 ? g_deg[r1] : 0;
        float inv0 = dg0 > 0 ? 0.8f / (float)dg0 : 0.f;
        float inv1 = dg1 > 0 ? 0.8f / (float)dg1 : 0.f;
        #pragma unroll
        for (int nt = 0; nt < 8; nt++) {
            int col = nt * 8 + 2 * kc;
            if (v0) {
                float2 f = *(const float2*)&feat[(size_t)r0 * FDIM + col];
                float2 o;
                if (dg0 > 0) {
                    o.x = fmaxf(fmaf(c[mt][nt][0], inv0, 0.2f * f.x), 0.f);
                    o.y = fmaxf(fmaf(c[mt][nt][1], inv0, 0.2f * f.y), 0.f);
                } else o = f;
                *(float2*)&out[(size_t)r0 * FDIM + col] = o;
            }
            if (v1) {
                float2 f = *(const float2*)&feat[(size_t)r1 * FDIM + col];
                float2 o;
                if (dg1 > 0) {
                    o.x = fmaxf(fmaf(c[mt][nt][2], inv1, 0.2f * f.x), 0.f);
                    o.y = fmaxf(fmaf(c[mt][nt][3], inv1, 0.2f * f.y), 0.f);
                } else o = f;
                *(float2*)&out[(size_t)r1 * FDIM + col] = o;
            }
        }
    }
}

// ---------------------------------------------------------------------------
extern "C" void kernel_launch(void* const* d_in, const int* in_sizes, int n_in,
                              void* d_out, int out_size) {
    const float* feat = (const float*)d_in[0];   // [50000, 64] f32
    const float* W    = (const float*)d_in[1];   // [8, 64, 64] f32
    const int*   src  = (const int*)d_in[2];     // [800000] i32
    const int*   dst  = (const int*)d_in[3];     // [800000] i32
    const int*   et   = (const int*)d_in[4];     // [800000] i32
    float* out = (float*)d_out;                  // [50000, 64] f32

    const size_t ZN = (size_t)N_NODES * (KDIM / 4);          // 6.4M float4
    k_zero<<<(int)((ZN + 255) / 256), 256>>>();
    k_pack_deg<<<(N_EDGES + 255) / 256, 256>>>(src, dst, et);
    k_scatter<<<(N_EDGES * 16 + 255) / 256, 256>>>((const float4*)feat);
    k_gemm_final<<<(N_NODES + 127) / 128, GEMM_THREADS>>>(feat, W, out);
}